// round 8
// baseline (speedup 1.0000x reference)
#include <cuda_runtime.h>
#include <cuda_bf16.h>
#include <cuda_fp16.h>
#include <cuda_fp8.h>
#include <cstdint>

#define NBATCH 131072
#define NH     100
#define TPB    128
#define TILEB  64
#define NPASS  6
#define NT     13          // n8 tiles (104 >= 100)
#define SPITCH 144         // fp8 tile pitch bytes (conflict-free LDS.32 frags)

// ---- SMEM layout ----
#define SM_S     0                  // 128 x 144 fp8 = 18432
#define SM_G2    18432              // 18432
#define SM_FRAG1 36864              // 32 lanes x 432 B = 13824
#define SM_FRAG2 50688              // 13824
#define SM_W1H   64512              // 128 rows x 16 B bf16 = 2048
#define SM_W1G   66560              // 16 rows x 240 B bf16 = 3840
#define SM_BW3   70400              // float4[52] = 832
#define SM_RES   71232              // float2[128] = 1024
#define SM_TOTAL 72256

#define BLOB_BYTES 34368            // FRAG1+FRAG2+W1H+W1G+BW3
#define OB_FRAG1 0
#define OB_FRAG2 13824
#define OB_W1H   27648
#define OB_W1G   29696
#define OB_BW3   33536

// scales: S,W2,w3,W1H x64 ; W1G x 2^-12
#define KINV12 2.44140625e-4f
#define C1S 4.0690104e-5f    // 2^-12/6
#define C2S 4.9670503e-10f   // 2^-24/120
#define C1C 1.220703125e-4f  // 2^-12/2
#define C2C 2.4835251e-9f    // 2^-24/24

__device__ __align__(16) unsigned char g_blob[NPASS][BLOB_BYTES];

__device__ __forceinline__ uint32_t smem_u32(const void* p) {
    uint32_t a;
    asm("{ .reg .u64 t; cvta.to.shared.u64 t, %1; cvt.u32.u64 %0, t; }" : "=r"(a) : "l"(p));
    return a;
}
__device__ __forceinline__ void ldsm4(uint32_t* r, uint32_t addr) {
    asm volatile("ldmatrix.sync.aligned.m8n8.x4.shared.b16 {%0,%1,%2,%3}, [%4];"
                 : "=r"(r[0]), "=r"(r[1]), "=r"(r[2]), "=r"(r[3]) : "r"(addr));
}
__device__ __forceinline__ void mma16816(float* d, const uint32_t* a, uint32_t b0, uint32_t b1) {
    asm volatile("mma.sync.aligned.m16n8k16.row.col.f32.bf16.bf16.f32 "
                 "{%0,%1,%2,%3}, {%4,%5,%6,%7}, {%8,%9}, {%0,%1,%2,%3};"
                 : "+f"(d[0]), "+f"(d[1]), "+f"(d[2]), "+f"(d[3])
                 : "r"(a[0]), "r"(a[1]), "r"(a[2]), "r"(a[3]), "r"(b0), "r"(b1));
}
__device__ __forceinline__ void mma16808(float* d, uint32_t a0, uint32_t a1, uint32_t b0) {
    asm volatile("mma.sync.aligned.m16n8k8.row.col.f32.bf16.bf16.f32 "
                 "{%0,%1,%2,%3}, {%4,%5}, {%6}, {%0,%1,%2,%3};"
                 : "+f"(d[0]), "+f"(d[1]), "+f"(d[2]), "+f"(d[3])
                 : "r"(a0), "r"(a1), "r"(b0));
}
__device__ __forceinline__ void mma16832f8(float* d, const uint32_t* a, uint32_t b0, uint32_t b1) {
    asm volatile("mma.sync.aligned.m16n8k32.row.col.f32.e4m3.e4m3.f32 "
                 "{%0,%1,%2,%3}, {%4,%5,%6,%7}, {%8,%9}, {%0,%1,%2,%3};"
                 : "+f"(d[0]), "+f"(d[1]), "+f"(d[2]), "+f"(d[3])
                 : "r"(a[0]), "r"(a[1]), "r"(a[2]), "r"(a[3]), "r"(b0), "r"(b1));
}
__device__ __forceinline__ uint32_t pack_bf2(float a, float b) {
    __nv_bfloat162 t = __floats2bfloat162_rn(a, b);
    return *reinterpret_cast<uint32_t*>(&t);
}
__device__ __forceinline__ uint32_t lds32(uint32_t a) {
    uint32_t v; asm volatile("ld.shared.b32 %0, [%1];" : "=r"(v) : "r"(a)); return v;
}
__device__ __forceinline__ void sts16(uint32_t a, unsigned short v) {
    asm volatile("st.shared.b16 [%0], %1;" :: "r"(a), "h"(v));
}
__device__ __forceinline__ unsigned short lds16(uint32_t a) {
    unsigned short v; asm volatile("ld.shared.b16 %0, [%1];" : "=h"(v) : "r"(a)); return v;
}
__device__ __forceinline__ unsigned short cvt2e4m3(float hi, float lo) {
    unsigned short v;
    asm("cvt.rn.satfinite.e4m3x2.f32 %0, %1, %2;" : "=h"(v) : "f"(hi), "f"(lo));
    return v;
}
__device__ __forceinline__ float2 e4m3x2_to_f2(unsigned short v) {
    uint32_t r;
    asm("cvt.rn.f16x2.e4m3x2 %0, %1;" : "=r"(r) : "h"(v));
    __half2 h = *reinterpret_cast<__half2*>(&r);
    return __half22float2(h);
}
__device__ __forceinline__ float sin64(float h64) {          // 64*sin(h64/64)
    float u = h64 * h64;
    return h64 * fmaf(u, fmaf(u, C2S, -C1S), 1.f);
}
__device__ __forceinline__ float cosp(float h) {             // cos(h), h small
    float u = h * h;
    return fmaf(u, fmaf(u, 4.1666667e-2f, -0.5f), 1.f);
}

// ------------------------------------------------------------------
__global__ void prep_kernel(
    const float* __restrict__ Wq1, const float* __restrict__ bq1,
    const float* __restrict__ Wq2, const float* __restrict__ bq2,
    const float* __restrict__ wq3,
    const float* __restrict__ Wp1, const float* __restrict__ bp1,
    const float* __restrict__ Wp2, const float* __restrict__ bp2,
    const float* __restrict__ wp3)
{
    const int net = blockIdx.x, layer = net >> 1, ph = net & 1;
    const float* W1 = (ph ? Wp1 : Wq1) + layer * NH * 3;
    const float* b1 = (ph ? bp1 : bq1) + layer * NH;
    const float* W2 = (ph ? Wp2 : Wq2) + layer * NH * NH;
    const float* b2 = (ph ? bp2 : bq2) + layer * NH;
    const float* w3 = (ph ? wp3 : wq3) + layer * NH;
    unsigned char* blob = g_blob[net];
    const int tid = threadIdx.x;

    for (int i = tid; i < BLOB_BYTES / 4; i += blockDim.x)
        reinterpret_cast<uint32_t*>(blob)[i] = 0u;
    __syncthreads();

    // fp8 fragment images: [lane][nt][kt][reg][i], per-lane stride 432B
    for (int idx = tid; idx < 32 * 13 * 32; idx += blockDim.x) {
        int lane = idx / 416, rem = idx % 416;
        int nt = rem / 32, r2 = rem % 32;
        int kt = r2 / 8, r3 = r2 % 8;
        int reg = r3 / 4, i = r3 % 4;
        int k = 32 * kt + 16 * reg + 4 * (lane & 3) + i;
        int n = 8 * nt + (lane >> 2);
        int off = lane * 432 + nt * 32 + kt * 8 + reg * 4 + i;
        unsigned char v1 = 0, v2 = 0;
        if (k < NH && n < NH) {
            v1 = __nv_cvt_float_to_fp8(64.f * W2[n * NH + k], __NV_SATFINITE, __NV_E4M3);
            v2 = __nv_cvt_float_to_fp8(64.f * W2[k * NH + n], __NV_SATFINITE, __NV_E4M3);
        }
        blob[OB_FRAG1 + off] = v1;
        blob[OB_FRAG2 + off] = v2;
    }
    // W1H: rows j, 8 bf16 [64wx,64wy,64wz,64b1,0,0,0,0]
    for (int j = tid; j < NH; j += blockDim.x) {
        __nv_bfloat16* r = reinterpret_cast<__nv_bfloat16*>(blob + OB_W1H + 16 * j);
        r[0] = __float2bfloat16(64.f * W1[3 * j]);
        r[1] = __float2bfloat16(64.f * W1[3 * j + 1]);
        r[2] = __float2bfloat16(64.f * W1[3 * j + 2]);
        r[3] = __float2bfloat16(64.f * b1[j]);
        // W1G rows 0/1 (x 2^-12), pitch 240
        *reinterpret_cast<__nv_bfloat16*>(blob + OB_W1G + 2 * j) =
            __float2bfloat16(W1[3 * j] * KINV12);
        *reinterpret_cast<__nv_bfloat16*>(blob + OB_W1G + 240 + 2 * j) =
            __float2bfloat16(W1[3 * j + 1] * KINV12);
    }
    // BW3: float4[4nt+c] = (b2[n], b2[n+1], 64w3[n], 64w3[n+1]), n = 8nt+2c
    for (int i = tid; i < 52; i += blockDim.x) {
        int n = 8 * (i >> 2) + 2 * (i & 3);
        float4 v = make_float4(0.f, 0.f, 0.f, 0.f);
        if (n < NH)
            v = make_float4(b2[n], b2[n + 1], 64.f * w3[n], 64.f * w3[n + 1]);
        reinterpret_cast<float4*>(blob + OB_BW3)[i] = v;
    }
}

// ------------------------------------------------------------------
// FP8 GEMM over one tile: acc += tile(A fp8 in smem) @ frag-image(B)
__device__ __forceinline__ void gemm_f8(uint32_t sbase, uint32_t tileOff, uint32_t fragOff,
                                        int w, int l, float acc[2][NT][4])
{
    const uint32_t aBase = sbase + tileOff + (32 * w + (l >> 2)) * SPITCH + 4 * (l & 3);
    const uint32_t bBase = sbase + fragOff + l * 432;
#pragma unroll
    for (int kt = 0; kt < 4; ++kt) {
        uint32_t a[2][4];
#pragma unroll
        for (int mt = 0; mt < 2; ++mt) {
            uint32_t ad = aBase + mt * 16 * SPITCH + 32 * kt;
            a[mt][0] = lds32(ad);
            a[mt][1] = lds32(ad + 8 * SPITCH);
            a[mt][2] = lds32(ad + 16);
            a[mt][3] = lds32(ad + 16 + 8 * SPITCH);
        }
#pragma unroll
        for (int nt = 0; nt < NT; ++nt) {
            uint32_t b0, b1;
            asm volatile("ld.shared.v2.u32 {%0,%1}, [%2];" : "=r"(b0), "=r"(b1)
                         : "r"(bBase + nt * 32 + kt * 8));
            mma16832f8(acc[0][nt], a[0], b0, b1);
            mma16832f8(acc[1][nt], a[1], b0, b1);
        }
    }
}

// ------------------------------------------------------------------
__global__ __launch_bounds__(TPB, 3)
void sympnet_fp8_kernel(const float* __restrict__ z, const float* __restrict__ tcol,
                        float* __restrict__ out)
{
    extern __shared__ unsigned char smem[];
    const uint32_t sbase = smem_u32(smem);

    const int tid = threadIdx.x;
    const int w = tid >> 5, l = tid & 31;
    const int rt = tid & 63;
    const int mof = tid >> 6;            // 0: tt=t rows, 1: tt=0 rows
    const int grow = blockIdx.x * TILEB + rt;

    const float4 z4 = reinterpret_cast<const float4*>(z)[grow];
    float q0 = z4.x, q1 = z4.y, p0 = z4.z, p1 = z4.w;
    const float tval = tcol[grow];
    const float tt_self = mof ? 0.f : tval;

    // zero pad cols [104,144) of S and G2 tiles (persist across passes)
    for (int i = tid; i < 128 * 10; i += TPB) {
        int r = i / 10, c = 104 + 4 * (i % 10);
        *reinterpret_cast<uint32_t*>(smem + SM_S  + r * SPITCH + c) = 0u;
        *reinterpret_cast<uint32_t*>(smem + SM_G2 + r * SPITCH + c) = 0u;
    }

    const uint32_t bW1h = sbase + SM_W1H + ((l & 7) + 8 * (l >> 3)) * 16;
    const uint32_t bW1g = sbase + SM_W1G + ((l & 7) + 8 * (l >> 4)) * 240 + 16 * ((l >> 3) & 1);
    const int rowA = 32 * w + (l >> 2);
    const uint32_t sRowS  = sbase + SM_S  + rowA * SPITCH;
    const uint32_t sRowG2 = sbase + SM_G2 + rowA * SPITCH;
    const int nOff = 2 * (l & 3);        // fp8 byte offset of this lane's n-pair

    const float4* bw3 = reinterpret_cast<const float4*>(smem + SM_BW3);
    float2* res = reinterpret_cast<float2*>(smem + SM_RES);

#pragma unroll 1
    for (int pass = 0; pass < NPASS; ++pass) {
        const int ph = pass & 1;

        // ---- weight blob copy ----
        {
            const uint4* s1 = reinterpret_cast<const uint4*>(g_blob[pass]);
            uint4* d1 = reinterpret_cast<uint4*>(smem + SM_FRAG1);
            for (int i = tid; i < BLOB_BYTES / 16; i += TPB) d1[i] = s1[i];
        }
        __syncthreads();

        const float x0 = ph ? p0 : q0;
        const float x1 = ph ? p1 : q1;

        float acc[2][NT][4];

        // ---- GEMM0: h64 = 64*(W1 @ [x;t] + b1), bf16 k=8 ----
        {
            uint32_t bh[4][4];
#pragma unroll
            for (int g = 0; g < 4; ++g) ldsm4(bh[g], bW1h + g * 512);
#pragma unroll
            for (int mt = 0; mt < 2; ++mt)
#pragma unroll
                for (int nt = 0; nt < NT; ++nt)
#pragma unroll
                    for (int c = 0; c < 4; ++c) acc[mt][nt][c] = 0.f;
#pragma unroll
            for (int mt = 0; mt < 2; ++mt) {
                const int s0i = 16 * mt + (l >> 2), s1i = s0i + 8;
                float xa0 = __shfl_sync(0xffffffffu, x0, s0i);
                float xa1 = __shfl_sync(0xffffffffu, x1, s0i);
                float ta  = __shfl_sync(0xffffffffu, tt_self, s0i);
                float xb0 = __shfl_sync(0xffffffffu, x0, s1i);
                float xb1 = __shfl_sync(0xffffffffu, x1, s1i);
                float tb  = __shfl_sync(0xffffffffu, tt_self, s1i);
                uint32_t a0 = 0u, a1 = 0u;
                if ((l & 3) == 0)      { a0 = pack_bf2(xa0, xa1); a1 = pack_bf2(xb0, xb1); }
                else if ((l & 3) == 1) { a0 = pack_bf2(ta, 1.f);  a1 = pack_bf2(tb, 1.f);  }
#pragma unroll
                for (int nt = 0; nt < NT; ++nt)
                    mma16808(acc[mt][nt], a0, a1, bh[nt >> 2][nt & 3]);
            }
        }

        // ---- s' = 64*sin(h) -> fp8 S tile ----
#pragma unroll
        for (int mt = 0; mt < 2; ++mt)
#pragma unroll
            for (int nt = 0; nt < NT; ++nt) {
                float s0 = sin64(acc[mt][nt][0]), s1 = sin64(acc[mt][nt][1]);
                float s2 = sin64(acc[mt][nt][2]), s3 = sin64(acc[mt][nt][3]);
                uint32_t ad = sRowS + mt * 16 * SPITCH + 8 * nt + nOff;
                sts16(ad,                cvt2e4m3(s1, s0));
                sts16(ad + 8 * SPITCH,   cvt2e4m3(s3, s2));
            }
        __syncwarp();

        // ---- GEMM1 (fp8): acc = 4096*(H2 - b2) ----
#pragma unroll
        for (int mt = 0; mt < 2; ++mt)
#pragma unroll
            for (int nt = 0; nt < NT; ++nt)
#pragma unroll
                for (int c = 0; c < 4; ++c) acc[mt][nt][c] = 0.f;
        gemm_f8(sbase, SM_S, SM_FRAG1, w, l, acc);

        // ---- g2' = 64*cos(h2)*w3 -> fp8 G2 tile ----
#pragma unroll
        for (int nt = 0; nt < NT; ++nt) {
            float4 bw = bw3[4 * nt + (l & 3)];
#pragma unroll
            for (int mt = 0; mt < 2; ++mt) {
                float g0 = cosp(fmaf(acc[mt][nt][0], KINV12, bw.x)) * bw.z;
                float g1 = cosp(fmaf(acc[mt][nt][1], KINV12, bw.y)) * bw.w;
                float g2 = cosp(fmaf(acc[mt][nt][2], KINV12, bw.x)) * bw.z;
                float g3 = cosp(fmaf(acc[mt][nt][3], KINV12, bw.y)) * bw.w;
                uint32_t ad = sRowG2 + mt * 16 * SPITCH + 8 * nt + nOff;
                sts16(ad,              cvt2e4m3(g1, g0));
                sts16(ad + 8 * SPITCH, cvt2e4m3(g3, g2));
            }
        }
        __syncwarp();

        // ---- GEMM2 (fp8): acc = 4096*GC ----
#pragma unroll
        for (int mt = 0; mt < 2; ++mt)
#pragma unroll
            for (int nt = 0; nt < NT; ++nt)
#pragma unroll
                for (int c = 0; c < 4; ++c) acc[mt][nt][c] = 0.f;
        gemm_f8(sbase, SM_G2, SM_FRAG2, w, l, acc);

        // ---- stage5: g1' = acc * cos(h1)  (cos from fp8 s') -> bf16 A-frags ----
        uint32_t af3[2][7][4];
#pragma unroll
        for (int mt = 0; mt < 2; ++mt)
#pragma unroll
            for (int nt = 0; nt < NT; ++nt) {
                uint32_t ad = sRowS + mt * 16 * SPITCH + 8 * nt + nOff;
                float2 sa = e4m3x2_to_f2(lds16(ad));
                float2 sb = e4m3x2_to_f2(lds16(ad + 8 * SPITCH));
                float v0 = sa.x * sa.x, v1 = sa.y * sa.y;
                float v2 = sb.x * sb.x, v3 = sb.y * sb.y;
                float c0 = fmaf(v0, fmaf(v0, C2C, -C1C), 1.f);
                float c1 = fmaf(v1, fmaf(v1, C2C, -C1C), 1.f);
                float c2 = fmaf(v2, fmaf(v2, C2C, -C1C), 1.f);
                float c3 = fmaf(v3, fmaf(v3, C2C, -C1C), 1.f);
                af3[mt][nt >> 1][2 * (nt & 1) + 0] =
                    pack_bf2(acc[mt][nt][0] * c0, acc[mt][nt][1] * c1);
                af3[mt][nt >> 1][2 * (nt & 1) + 1] =
                    pack_bf2(acc[mt][nt][2] * c2, acc[mt][nt][3] * c3);
            }
#pragma unroll
        for (int mt = 0; mt < 2; ++mt) { af3[mt][6][2] = 0u; af3[mt][6][3] = 0u; }

        // ---- GEMM3: grad = G1' @ (W1[:, :2] * 2^-12), bf16 ----
        float acc3[2][4];
#pragma unroll
        for (int mt = 0; mt < 2; ++mt)
#pragma unroll
            for (int c = 0; c < 4; ++c) acc3[mt][c] = 0.f;
#pragma unroll
        for (int kt = 0; kt < 7; ++kt) {
            uint32_t bg[4];
            ldsm4(bg, bW1g + 32 * kt);
#pragma unroll
            for (int mt = 0; mt < 2; ++mt)
                mma16816(acc3[mt], af3[mt][kt], bg[0], bg[1]);
        }

        // ---- exchange gg = grad(t) - grad(0), update ----
        if ((l & 3) == 0) {
#pragma unroll
            for (int mt = 0; mt < 2; ++mt) {
                int r0 = 32 * w + 16 * mt + (l >> 2);
                res[r0]     = make_float2(acc3[mt][0], acc3[mt][1]);
                res[r0 + 8] = make_float2(acc3[mt][2], acc3[mt][3]);
            }
        }
        __syncthreads();
        const float2 ga = res[rt], gb = res[64 + rt];
        const float g0 = ga.x - gb.x, g1 = ga.y - gb.y;
        if (ph == 0) { p0 -= g0; p1 -= g1; }
        else         { q0 += g0; q1 += g1; }
        __syncthreads();
    }

    if (mof == 0)
        reinterpret_cast<float4*>(out)[grow] = make_float4(q0, q1, p0, p1);
}

// ------------------------------------------------------------------
extern "C" void kernel_launch(void* const* d_in, const int* in_sizes, int n_in,
                              void* d_out, int out_size)
{
    const float* z   = (const float*)d_in[0];
    const float* t   = (const float*)d_in[1];
    const float* Wq1 = (const float*)d_in[2];
    const float* bq1 = (const float*)d_in[3];
    const float* Wq2 = (const float*)d_in[4];
    const float* bq2 = (const float*)d_in[5];
    const float* wq3 = (const float*)d_in[6];
    const float* Wp1 = (const float*)d_in[7];
    const float* bp1 = (const float*)d_in[8];
    const float* Wp2 = (const float*)d_in[9];
    const float* bp2 = (const float*)d_in[10];
    const float* wp3 = (const float*)d_in[11];
    float* out = (float*)d_out;

    cudaFuncSetAttribute(sympnet_fp8_kernel,
                         cudaFuncAttributeMaxDynamicSharedMemorySize, SM_TOTAL);

    prep_kernel<<<NPASS, 256>>>(Wq1, bq1, Wq2, bq2, wq3, Wp1, bp1, Wp2, bp2, wp3);
    sympnet_fp8_kernel<<<NBATCH / TILEB, TPB, SM_TOTAL>>>(z, t, out);
}

// round 9
// speedup vs baseline: 1.5654x; 1.5654x over previous
#include <cuda_runtime.h>
#include <cuda_bf16.h>
#include <cstdint>

#define NBATCH 131072
#define NH   100
#define SP   120           // tile pitch (bf16 elems) = 240B, ldmatrix conflict-free
#define SPB  (SP * 2)
#define TPB  128
#define TILEB 64
#define NPASS 6
#define KT   7             // k16 tiles
#define NT   13            // n8 tiles (104 >= 100)
#define NTP  7

// ---- SMEM layout ----
#define SM_S     0                      // 128 x SP bf16 = 30720
#define SM_W2    30720                  // 112 x SP bf16 = 26880 (b2 folded in col 104)
#define SM_W1H   57600                  // 128 rows x 16B = 2048
#define SM_W3    59648                  // float2[56] = 448
#define SM_W1G0  60096                  // 16 rows x 240B = 3840 (double buffered)
#define SM_W1G1  63936                  // 3840
#define SM_TOTAL 67776                  // -> 3 CTAs/SM

// ---- weight blob: [ W2 | W1H | W3 ] (region A) + [ W1G ] (region B) ----
#define OB_W1H 26880
#define OB_W3  28928
#define REGA_BYTES 29376
#define OB_W1G 29376
#define BLOB_BYTES 33216

__device__ __align__(16) unsigned char g_blob[NPASS][BLOB_BYTES];

__device__ __forceinline__ uint32_t smem_u32(const void* p) {
    uint32_t a;
    asm("{ .reg .u64 t; cvta.to.shared.u64 t, %1; cvt.u32.u64 %0, t; }" : "=r"(a) : "l"(p));
    return a;
}
__device__ __forceinline__ void ldsm4(uint32_t* r, uint32_t addr) {
    asm volatile("ldmatrix.sync.aligned.m8n8.x4.shared.b16 {%0,%1,%2,%3}, [%4];"
                 : "=r"(r[0]), "=r"(r[1]), "=r"(r[2]), "=r"(r[3]) : "r"(addr));
}
__device__ __forceinline__ void ldsm4t(uint32_t* r, uint32_t addr) {
    asm volatile("ldmatrix.sync.aligned.m8n8.x4.trans.shared.b16 {%0,%1,%2,%3}, [%4];"
                 : "=r"(r[0]), "=r"(r[1]), "=r"(r[2]), "=r"(r[3]) : "r"(addr));
}
__device__ __forceinline__ void mma16816(float* d, const uint32_t* a, uint32_t b0, uint32_t b1) {
    asm volatile("mma.sync.aligned.m16n8k16.row.col.f32.bf16.bf16.f32 "
                 "{%0,%1,%2,%3}, {%4,%5,%6,%7}, {%8,%9}, {%0,%1,%2,%3};"
                 : "+f"(d[0]), "+f"(d[1]), "+f"(d[2]), "+f"(d[3])
                 : "r"(a[0]), "r"(a[1]), "r"(a[2]), "r"(a[3]), "r"(b0), "r"(b1));
}
__device__ __forceinline__ void mma16808(float* d, uint32_t a0, uint32_t a1, uint32_t b0) {
    asm volatile("mma.sync.aligned.m16n8k8.row.col.f32.bf16.bf16.f32 "
                 "{%0,%1,%2,%3}, {%4,%5}, {%6}, {%0,%1,%2,%3};"
                 : "+f"(d[0]), "+f"(d[1]), "+f"(d[2]), "+f"(d[3])
                 : "r"(a0), "r"(a1), "r"(b0));
}
__device__ __forceinline__ void cp16(uint32_t smem_dst, const void* gsrc) {
    asm volatile("cp.async.cg.shared.global [%0], [%1], 16;"
                 :: "r"(smem_dst), "l"(gsrc));
}
__device__ __forceinline__ uint32_t pack_bf2(float a, float b) {
    __nv_bfloat162 t = __floats2bfloat162_rn(a, b);
    return *reinterpret_cast<uint32_t*>(&t);
}
__device__ __forceinline__ float sinp(float h) {
    float h2 = h * h;
    return h * fmaf(h2, fmaf(h2, 8.3333333e-3f, -1.6666667e-1f), 1.f);
}
__device__ __forceinline__ float cosp(float h) {
    float h2 = h * h;
    return fmaf(h2, fmaf(h2, 4.1666667e-2f, -0.5f), 1.f);
}

// ------------------------------------------------------------------
__global__ void prep_kernel(
    const float* __restrict__ Wq1, const float* __restrict__ bq1,
    const float* __restrict__ Wq2, const float* __restrict__ bq2,
    const float* __restrict__ wq3,
    const float* __restrict__ Wp1, const float* __restrict__ bp1,
    const float* __restrict__ Wp2, const float* __restrict__ bp2,
    const float* __restrict__ wp3)
{
    const int net = blockIdx.x, layer = net >> 1, ph = net & 1;
    const float* W1 = (ph ? Wp1 : Wq1) + layer * NH * 3;
    const float* b1 = (ph ? bp1 : bq1) + layer * NH;
    const float* W2 = (ph ? Wp2 : Wq2) + layer * NH * NH;
    const float* b2 = (ph ? bp2 : bq2) + layer * NH;
    const float* w3 = (ph ? wp3 : wq3) + layer * NH;
    unsigned char* blob = g_blob[net];
    const int tid = threadIdx.x;

    for (int i = tid; i < BLOB_BYTES / 4; i += blockDim.x)
        reinterpret_cast<uint32_t*>(blob)[i] = 0u;
    __syncthreads();

    for (int idx = tid; idx < NH * NH; idx += blockDim.x) {
        int n = idx / NH, k = idx % NH;
        *reinterpret_cast<__nv_bfloat16*>(blob + n * SPB + 2 * k) = __float2bfloat16(W2[idx]);
    }
    for (int n = tid; n < NH; n += blockDim.x)
        *reinterpret_cast<__nv_bfloat16*>(blob + n * SPB + 208) = __float2bfloat16(b2[n]); // k=104
    for (int j = tid; j < NH; j += blockDim.x) {
        __nv_bfloat16* r = reinterpret_cast<__nv_bfloat16*>(blob + OB_W1H + 16 * j);
        r[0] = __float2bfloat16(W1[3 * j]);
        r[1] = __float2bfloat16(W1[3 * j + 1]);
        r[2] = __float2bfloat16(W1[3 * j + 2]);
        r[3] = __float2bfloat16(b1[j]);
        *reinterpret_cast<__nv_bfloat16*>(blob + OB_W1G + 2 * j)       = __float2bfloat16(W1[3 * j]);
        *reinterpret_cast<__nv_bfloat16*>(blob + OB_W1G + 240 + 2 * j) = __float2bfloat16(W1[3 * j + 1]);
    }
    for (int i = tid; 2 * i < NH; i += blockDim.x)
        reinterpret_cast<float2*>(blob + OB_W3)[i] = make_float2(w3[2 * i], w3[2 * i + 1]);
}

// ------------------------------------------------------------------
__global__ __launch_bounds__(TPB, 3)
void sympnet_mma_kernel(const float* __restrict__ z, const float* __restrict__ tcol,
                        float* __restrict__ out)
{
    extern __shared__ unsigned char smem[];
    const uint32_t sbase = smem_u32(smem);

    const int tid = threadIdx.x;
    const int w = tid >> 5, l = tid & 31;
    const int el = l & 15;               // batch element within warp (lanes 16-31 duplicate)
    const int grow = blockIdx.x * TILEB + 16 * w + el;

    // prologue: prefetch pass-0 weights
    {
        const unsigned char* src = g_blob[0];
        for (int i = tid; i < REGA_BYTES / 16; i += TPB)
            cp16(sbase + SM_W2 + 16 * i, src + 16 * i);
        for (int i = tid; i < 3840 / 16; i += TPB)
            cp16(sbase + SM_W1G0 + 16 * i, src + OB_W1G + 16 * i);
        asm volatile("cp.async.commit_group;");
    }

    const float4 z4 = reinterpret_cast<const float4*>(z)[grow];
    float q0 = z4.x, q1 = z4.y, p0 = z4.z, p1 = z4.w;
    const float tval = tcol[grow];

    // zero pad cols [100,120) of the S tile (persist across passes)
    for (int i = tid; i < 128 * 10; i += TPB) {
        int r = i / 10, c = NH + 2 * (i % 10);
        *reinterpret_cast<uint32_t*>(smem + SM_S + r * SPB + c * 2) = 0u;
    }

    // ldmatrix bases
    const uint32_t bW2  = sbase + SM_W2  + ((l & 7) + 8 * (l >> 4)) * SPB + 16 * ((l >> 3) & 1);
    const uint32_t bW2t = sbase + SM_W2  + ((l & 7) + 8 * ((l >> 3) & 1)) * SPB + 16 * (l >> 4);
    const uint32_t bW1h = sbase + SM_W1H + ((l & 7) + 8 * (l >> 3)) * 16;
    const uint32_t bW1gL = ((l & 7) + 8 * (l >> 4)) * 240 + 16 * ((l >> 3) & 1);
    const uint32_t sS0  = sbase + SM_S   + (32 * w + (l >> 2)) * SPB + 4 * (l & 3);

    const float2* w3p = reinterpret_cast<const float2*>(smem + SM_W3);
    const uint32_t biasA = ((l & 3) == 0) ? 0x00003F80u : 0u;   // bf16 1.0 at k=104
    const int r0 = l >> 2, r1 = r0 + 8;

#pragma unroll 1
    for (int pass = 0; pass < NPASS; ++pass) {
        const int ph = pass & 1;

        asm volatile("cp.async.wait_group 0;" ::: "memory");
        __syncthreads();   // this pass's weights visible; prior reads complete

        const float x0 = ph ? p0 : q0;
        const float x1 = ph ? p1 : q1;

        float acc[2][NT][4];

        // ---- GEMM0: h1 = [x0,x1,tt,1] @ [W1|b1]^T  (mt = branch: 0 -> t, 1 -> 0) ----
        {
            uint32_t bh[4][4];
#pragma unroll
            for (int g = 0; g < 4; ++g) ldsm4(bh[g], bW1h + g * 512);
#pragma unroll
            for (int mt = 0; mt < 2; ++mt)
#pragma unroll
                for (int nt = 0; nt < NT; ++nt)
#pragma unroll
                    for (int c = 0; c < 4; ++c) acc[mt][nt][c] = 0.f;

            const float xa0 = __shfl_sync(0xffffffffu, x0, r0);
            const float xa1 = __shfl_sync(0xffffffffu, x1, r0);
            const float xb0 = __shfl_sync(0xffffffffu, x0, r1);
            const float xb1 = __shfl_sync(0xffffffffu, x1, r1);
            const float ta  = __shfl_sync(0xffffffffu, tval, r0);
            const float tb  = __shfl_sync(0xffffffffu, tval, r1);
#pragma unroll
            for (int mt = 0; mt < 2; ++mt) {
                uint32_t a0 = 0u, a1 = 0u;
                if ((l & 3) == 0)      { a0 = pack_bf2(xa0, xa1); a1 = pack_bf2(xb0, xb1); }
                else if ((l & 3) == 1) { a0 = pack_bf2(mt ? 0.f : ta, 1.f);
                                         a1 = pack_bf2(mt ? 0.f : tb, 1.f); }
#pragma unroll
                for (int nt = 0; nt < NT; ++nt)
                    mma16808(acc[mt][nt], a0, a1, bh[nt >> 2][nt & 3]);
            }
        }

        // ---- sin -> GEMM1 A-fragments + warp-local S store ----
        uint32_t spk[2][NT][2];
#pragma unroll
        for (int mt = 0; mt < 2; ++mt)
#pragma unroll
            for (int nt = 0; nt < NT; ++nt) {
                spk[mt][nt][0] = pack_bf2(sinp(acc[mt][nt][0]), sinp(acc[mt][nt][1]));
                spk[mt][nt][1] = pack_bf2(sinp(acc[mt][nt][2]), sinp(acc[mt][nt][3]));
                uint32_t ad = sS0 + mt * 16 * SPB + nt * 16;
                asm volatile("st.shared.b32 [%0], %1;" :: "r"(ad), "r"(spk[mt][nt][0]));
                asm volatile("st.shared.b32 [%0], %1;" :: "r"(ad + 8 * SPB), "r"(spk[mt][nt][1]));
            }

        // ---- GEMM1: H2 = S @ W2^T (+b2 via k=104 one-column) ----
#pragma unroll
        for (int mt = 0; mt < 2; ++mt)
#pragma unroll
            for (int nt = 0; nt < NT; ++nt)
#pragma unroll
                for (int c = 0; c < 4; ++c) acc[mt][nt][c] = 0.f;
#pragma unroll
        for (int kt = 0; kt < KT; ++kt) {
            uint32_t b[NTP][4];
#pragma unroll
            for (int np = 0; np < NTP; ++np)
                ldsm4(b[np], bW2 + 32 * kt + np * 16 * SPB);
#pragma unroll
            for (int mt = 0; mt < 2; ++mt) {
                uint32_t a[4];
                a[0] = spk[mt][2 * kt][0];
                a[1] = spk[mt][2 * kt][1];
                a[2] = (kt < 6) ? spk[mt][2 * kt + 1][0] : biasA;
                a[3] = (kt < 6) ? spk[mt][2 * kt + 1][1] : biasA;
#pragma unroll
                for (int np = 0; np < NTP; ++np) {
                    mma16816(acc[mt][2 * np], a, b[np][0], b[np][1]);
                    if (2 * np + 1 < NT)
                        mma16816(acc[mt][2 * np + 1], a, b[np][2], b[np][3]);
                }
            }
        }

        // ---- stage3: g2 = cos(h2) * w3 -> GEMM2 A-fragments ----
        uint32_t af[2][KT][4];
#pragma unroll
        for (int nt = 0; nt < NT; ++nt) {
            const float2 wp = w3p[4 * nt + (l & 3)];
#pragma unroll
            for (int mt = 0; mt < 2; ++mt) {
                float g0 = cosp(acc[mt][nt][0]) * wp.x;
                float g1 = cosp(acc[mt][nt][1]) * wp.y;
                float g2 = cosp(acc[mt][nt][2]) * wp.x;
                float g3 = cosp(acc[mt][nt][3]) * wp.y;
                af[mt][nt >> 1][2 * (nt & 1) + 0] = pack_bf2(g0, g1);
                af[mt][nt >> 1][2 * (nt & 1) + 1] = pack_bf2(g2, g3);
            }
        }
#pragma unroll
        for (int mt = 0; mt < 2; ++mt) { af[mt][6][2] = 0u; af[mt][6][3] = 0u; }

        // ---- GEMM2: GC = G2 @ W2 (B = trans-ldsm of W2 tile) ----
#pragma unroll
        for (int mt = 0; mt < 2; ++mt)
#pragma unroll
            for (int nt = 0; nt < NT; ++nt)
#pragma unroll
                for (int c = 0; c < 4; ++c) acc[mt][nt][c] = 0.f;
#pragma unroll
        for (int kt = 0; kt < KT; ++kt) {
            uint32_t b[NTP][4];
#pragma unroll
            for (int np = 0; np < NTP; ++np)
                ldsm4t(b[np], bW2t + 16 * kt * SPB + 32 * np);
#pragma unroll
            for (int mt = 0; mt < 2; ++mt)
#pragma unroll
                for (int np = 0; np < NTP; ++np) {
                    mma16816(acc[mt][2 * np], af[mt][kt], b[np][0], b[np][1]);
                    if (2 * np + 1 < NT)
                        mma16816(acc[mt][2 * np + 1], af[mt][kt], b[np][2], b[np][3]);
                }
        }

        // ---- all warps done with W2/W1H/W3: prefetch next pass's weights ----
        __syncthreads();
        if (pass + 1 < NPASS) {
            const unsigned char* src = g_blob[pass + 1];
            for (int i = tid; i < REGA_BYTES / 16; i += TPB)
                cp16(sbase + SM_W2 + 16 * i, src + 16 * i);
            const uint32_t dstG = sbase + (((pass + 1) & 1) ? SM_W1G1 : SM_W1G0);
            for (int i = tid; i < 3840 / 16; i += TPB)
                cp16(dstG + 16 * i, src + OB_W1G + 16 * i);
            asm volatile("cp.async.commit_group;");
        }

        // ---- stage5: g1 = gc * cos(h1) -> GEMM3 A-fragments (warp-local S) ----
        uint32_t af3[2][KT][4];
#pragma unroll
        for (int mt = 0; mt < 2; ++mt)
#pragma unroll
            for (int nt = 0; nt < NT; ++nt) {
                uint32_t ad = sS0 + mt * 16 * SPB + nt * 16;
                uint32_t u01, u23;
                asm("ld.shared.b32 %0, [%1];" : "=r"(u01) : "r"(ad));
                asm("ld.shared.b32 %0, [%1];" : "=r"(u23) : "r"(ad + 8 * SPB));
                __nv_bfloat162 s01 = *reinterpret_cast<__nv_bfloat162*>(&u01);
                __nv_bfloat162 s23 = *reinterpret_cast<__nv_bfloat162*>(&u23);
                float s0 = __low2float(s01), s1 = __high2float(s01);
                float s2 = __low2float(s23), s3 = __high2float(s23);
                float v0 = s0 * s0, v1 = s1 * s1, v2 = s2 * s2, v3 = s3 * s3;
                float c0 = fmaf(-v0, fmaf(0.125f, v0, 0.5f), 1.f);
                float c1 = fmaf(-v1, fmaf(0.125f, v1, 0.5f), 1.f);
                float c2 = fmaf(-v2, fmaf(0.125f, v2, 0.5f), 1.f);
                float c3 = fmaf(-v3, fmaf(0.125f, v3, 0.5f), 1.f);
                af3[mt][nt >> 1][2 * (nt & 1) + 0] =
                    pack_bf2(acc[mt][nt][0] * c0, acc[mt][nt][1] * c1);
                af3[mt][nt >> 1][2 * (nt & 1) + 1] =
                    pack_bf2(acc[mt][nt][2] * c2, acc[mt][nt][3] * c3);
            }
#pragma unroll
        for (int mt = 0; mt < 2; ++mt) { af3[mt][6][2] = 0u; af3[mt][6][3] = 0u; }

        // ---- GEMM3: grad = G1 @ W1[:, :2]  (current pass's W1G buffer) ----
        float acc3[2][4];
#pragma unroll
        for (int mt = 0; mt < 2; ++mt)
#pragma unroll
            for (int c = 0; c < 4; ++c) acc3[mt][c] = 0.f;
        {
            const uint32_t bW1g = sbase + ((pass & 1) ? SM_W1G1 : SM_W1G0) + bW1gL;
#pragma unroll
            for (int kt = 0; kt < KT; ++kt) {
                uint32_t bg[4];
                ldsm4(bg, bW1g + 32 * kt);
#pragma unroll
                for (int mt = 0; mt < 2; ++mt)
                    mma16816(acc3[mt], af3[mt][kt], bg[0], bg[1]);
            }
        }

        // ---- gg = grad(t) - grad(0): register diff + intra-warp shuffles ----
        float d0 = acc3[0][0] - acc3[1][0];
        float d1 = acc3[0][1] - acc3[1][1];
        float d2 = acc3[0][2] - acc3[1][2];
        float d3 = acc3[0][3] - acc3[1][3];
        const int h = 4 * (el & 7);
        float s0 = __shfl_sync(0xffffffffu, d0, h);
        float s1 = __shfl_sync(0xffffffffu, d1, h);
        float s2 = __shfl_sync(0xffffffffu, d2, h);
        float s3 = __shfl_sync(0xffffffffu, d3, h);
        const float g0 = (el < 8) ? s0 : s2;
        const float g1 = (el < 8) ? s1 : s3;
        if (ph == 0) { p0 -= g0; p1 -= g1; }
        else         { q0 += g0; q1 += g1; }
    }

    if (l < 16)
        reinterpret_cast<float4*>(out)[grow] = make_float4(q0, q1, p0, p1);
}

// ------------------------------------------------------------------
extern "C" void kernel_launch(void* const* d_in, const int* in_sizes, int n_in,
                              void* d_out, int out_size)
{
    const float* z   = (const float*)d_in[0];
    const float* t   = (const float*)d_in[1];
    const float* Wq1 = (const float*)d_in[2];
    const float* bq1 = (const float*)d_in[3];
    const float* Wq2 = (const float*)d_in[4];
    const float* bq2 = (const float*)d_in[5];
    const float* wq3 = (const float*)d_in[6];
    const float* Wp1 = (const float*)d_in[7];
    const float* bp1 = (const float*)d_in[8];
    const float* Wp2 = (const float*)d_in[9];
    const float* bp2 = (const float*)d_in[10];
    const float* wp3 = (const float*)d_in[11];
    float* out = (float*)d_out;

    cudaFuncSetAttribute(sympnet_mma_kernel,
                         cudaFuncAttributeMaxDynamicSharedMemorySize, SM_TOTAL);

    prep_kernel<<<NPASS, 256>>>(Wq1, bq1, Wq2, bq2, wq3, Wp1, bp1, Wp2, bp2, wp3);
    sympnet_mma_kernel<<<NBATCH / TILEB, TPB, SM_TOTAL>>>(z, t, out);
}

// round 10
// speedup vs baseline: 1.9374x; 1.2376x over previous
#include <cuda_runtime.h>
#include <cuda_bf16.h>
#include <cstdint>

#define NBATCH 131072
#define NH   100
#define SP   120           // W2 tile pitch (bf16) = 240B, ldmatrix conflict-free
#define SPB  (SP * 2)
#define TPB  128
#define TILEB 64
#define NPASS 6
#define KT   7             // k16 tiles
#define NT   13            // n8 tiles (104 >= 100)
#define NTP  7

// ---- SMEM layout ----
#define SM_SCR   0                      // 4 warps x 26 pairs x 32 lanes x 8B = 26624
#define SM_W2    26624                  // 112 x SP bf16 = 26880 (b2 folded in col 104)
#define SM_W1H   53504                  // 128 rows x 16B = 2048
#define SM_W3    55552                  // packed bf16x2 w3: 256
#define SM_W1G0  55808                  // 16 rows x 240B = 3840 (double buffered)
#define SM_W1G1  59648                  // 3840
#define SM_TOTAL 63488                  // -> 3 CTAs/SM

// ---- weight blob: [ W2 | W1H | W3pk ] (region A) + [ W1G ] (region B) ----
#define OB_W1H 26880
#define OB_W3  28928
#define REGA_BYTES 29184
#define OB_W1G 29184
#define BLOB_BYTES 33024

__device__ __align__(16) unsigned char g_blob[NPASS][BLOB_BYTES];

__device__ __forceinline__ uint32_t smem_u32(const void* p) {
    uint32_t a;
    asm("{ .reg .u64 t; cvta.to.shared.u64 t, %1; cvt.u32.u64 %0, t; }" : "=r"(a) : "l"(p));
    return a;
}
__device__ __forceinline__ void ldsm4(uint32_t* r, uint32_t addr) {
    asm volatile("ldmatrix.sync.aligned.m8n8.x4.shared.b16 {%0,%1,%2,%3}, [%4];"
                 : "=r"(r[0]), "=r"(r[1]), "=r"(r[2]), "=r"(r[3]) : "r"(addr));
}
__device__ __forceinline__ void ldsm4t(uint32_t* r, uint32_t addr) {
    asm volatile("ldmatrix.sync.aligned.m8n8.x4.trans.shared.b16 {%0,%1,%2,%3}, [%4];"
                 : "=r"(r[0]), "=r"(r[1]), "=r"(r[2]), "=r"(r[3]) : "r"(addr));
}
__device__ __forceinline__ void mma16816(float* d, const uint32_t* a, uint32_t b0, uint32_t b1) {
    asm volatile("mma.sync.aligned.m16n8k16.row.col.f32.bf16.bf16.f32 "
                 "{%0,%1,%2,%3}, {%4,%5,%6,%7}, {%8,%9}, {%0,%1,%2,%3};"
                 : "+f"(d[0]), "+f"(d[1]), "+f"(d[2]), "+f"(d[3])
                 : "r"(a[0]), "r"(a[1]), "r"(a[2]), "r"(a[3]), "r"(b0), "r"(b1));
}
__device__ __forceinline__ void mma16808(float* d, uint32_t a0, uint32_t a1, uint32_t b0) {
    asm volatile("mma.sync.aligned.m16n8k8.row.col.f32.bf16.bf16.f32 "
                 "{%0,%1,%2,%3}, {%4,%5}, {%6}, {%0,%1,%2,%3};"
                 : "+f"(d[0]), "+f"(d[1]), "+f"(d[2]), "+f"(d[3])
                 : "r"(a0), "r"(a1), "r"(b0));
}
__device__ __forceinline__ void cp16(uint32_t smem_dst, const void* gsrc) {
    asm volatile("cp.async.cg.shared.global [%0], [%1], 16;"
                 :: "r"(smem_dst), "l"(gsrc));
}
__device__ __forceinline__ uint32_t pack_bf2(float a, float b) {
    __nv_bfloat162 t = __floats2bfloat162_rn(a, b);
    return *reinterpret_cast<uint32_t*>(&t);
}
__device__ __forceinline__ uint32_t hmul2u(uint32_t a, uint32_t b) {
    __nv_bfloat162 r = __hmul2(*reinterpret_cast<__nv_bfloat162*>(&a),
                               *reinterpret_cast<__nv_bfloat162*>(&b));
    return *reinterpret_cast<uint32_t*>(&r);
}
__device__ __forceinline__ uint32_t hfma2u(uint32_t a, uint32_t b, uint32_t c) {
    __nv_bfloat162 r = __hfma2(*reinterpret_cast<__nv_bfloat162*>(&a),
                               *reinterpret_cast<__nv_bfloat162*>(&b),
                               *reinterpret_cast<__nv_bfloat162*>(&c));
    return *reinterpret_cast<uint32_t*>(&r);
}
#define NEGH2 0xBF00BF00u   // bf16x2 {-0.5,-0.5}
#define ONE2  0x3F803F80u   // bf16x2 {1,1}

__device__ __forceinline__ float sinp(float h) {   // |h|<=0.15: err ~4e-6 rel
    return h * fmaf(h * h, -1.6666667e-1f, 1.f);
}

// ------------------------------------------------------------------
__global__ void prep_kernel(
    const float* __restrict__ Wq1, const float* __restrict__ bq1,
    const float* __restrict__ Wq2, const float* __restrict__ bq2,
    const float* __restrict__ wq3,
    const float* __restrict__ Wp1, const float* __restrict__ bp1,
    const float* __restrict__ Wp2, const float* __restrict__ bp2,
    const float* __restrict__ wp3)
{
    const int net = blockIdx.x, layer = net >> 1, ph = net & 1;
    const float* W1 = (ph ? Wp1 : Wq1) + layer * NH * 3;
    const float* b1 = (ph ? bp1 : bq1) + layer * NH;
    const float* W2 = (ph ? Wp2 : Wq2) + layer * NH * NH;
    const float* b2 = (ph ? bp2 : bq2) + layer * NH;
    const float* w3 = (ph ? wp3 : wq3) + layer * NH;
    unsigned char* blob = g_blob[net];
    const int tid = threadIdx.x;

    for (int i = tid; i < BLOB_BYTES / 4; i += blockDim.x)
        reinterpret_cast<uint32_t*>(blob)[i] = 0u;
    __syncthreads();

    for (int idx = tid; idx < NH * NH; idx += blockDim.x) {
        int n = idx / NH, k = idx % NH;
        *reinterpret_cast<__nv_bfloat16*>(blob + n * SPB + 2 * k) = __float2bfloat16(W2[idx]);
    }
    for (int n = tid; n < NH; n += blockDim.x)
        *reinterpret_cast<__nv_bfloat16*>(blob + n * SPB + 208) = __float2bfloat16(b2[n]); // k=104
    for (int j = tid; j < NH; j += blockDim.x) {
        __nv_bfloat16* r = reinterpret_cast<__nv_bfloat16*>(blob + OB_W1H + 16 * j);
        r[0] = __float2bfloat16(W1[3 * j]);
        r[1] = __float2bfloat16(W1[3 * j + 1]);
        r[2] = __float2bfloat16(W1[3 * j + 2]);
        r[3] = __float2bfloat16(b1[j]);
        *reinterpret_cast<__nv_bfloat16*>(blob + OB_W1G + 2 * j)       = __float2bfloat16(W1[3 * j]);
        *reinterpret_cast<__nv_bfloat16*>(blob + OB_W1G + 240 + 2 * j) = __float2bfloat16(W1[3 * j + 1]);
    }
    // packed bf16x2 w3: idx 4nt+c -> (w3[8nt+2c], w3[8nt+2c+1])
    for (int i = tid; i < 52; i += blockDim.x) {
        int n = 8 * (i >> 2) + 2 * (i & 3);
        uint32_t v = 0u;
        if (n + 1 < NH) {
            __nv_bfloat162 t = __floats2bfloat162_rn(w3[n], w3[n + 1]);
            v = *reinterpret_cast<uint32_t*>(&t);
        }
        reinterpret_cast<uint32_t*>(blob + OB_W3)[i] = v;
    }
}

// ------------------------------------------------------------------
__global__ __launch_bounds__(TPB, 3)
void sympnet_mma_kernel(const float* __restrict__ z, const float* __restrict__ tcol,
                        float* __restrict__ out)
{
    extern __shared__ unsigned char smem[];
    const uint32_t sbase = smem_u32(smem);

    const int tid = threadIdx.x;
    const int w = tid >> 5, l = tid & 31;
    const int el = l & 15;               // batch element within warp (lanes 16-31 duplicate)
    const int grow = blockIdx.x * TILEB + 16 * w + el;

    // prologue: prefetch pass-0 weights
    {
        const unsigned char* src = g_blob[0];
        for (int i = tid; i < REGA_BYTES / 16; i += TPB)
            cp16(sbase + SM_W2 + 16 * i, src + 16 * i);
        for (int i = tid; i < 3840 / 16; i += TPB)
            cp16(sbase + SM_W1G0 + 16 * i, src + OB_W1G + 16 * i);
        asm volatile("cp.async.commit_group;");
    }

    const float4 z4 = reinterpret_cast<const float4*>(z)[grow];
    float q0 = z4.x, q1 = z4.y, p0 = z4.z, p1 = z4.w;
    const float tval = tcol[grow];

    // ldmatrix / scratch bases
    const uint32_t bW2  = sbase + SM_W2  + ((l & 7) + 8 * (l >> 4)) * SPB + 16 * ((l >> 3) & 1);
    const uint32_t bW2t = sbase + SM_W2  + ((l & 7) + 8 * ((l >> 3) & 1)) * SPB + 16 * (l >> 4);
    const uint32_t bW1h = sbase + SM_W1H + ((l & 7) + 8 * (l >> 3)) * 16;
    const uint32_t bW1gL = ((l & 7) + 8 * (l >> 4)) * 240 + 16 * ((l >> 3) & 1);
    const uint32_t sScr = sbase + SM_SCR + w * 6656 + l * 8;   // fragment-order S scratch

    const uint32_t* w3pk = reinterpret_cast<const uint32_t*>(smem + SM_W3);
    const uint32_t biasA = ((l & 3) == 0) ? 0x00003F80u : 0u;   // bf16 1.0 at k=104
    const int r0 = l >> 2, r1 = r0 + 8;

#pragma unroll 1
    for (int pass = 0; pass < NPASS; ++pass) {
        const int ph = pass & 1;

        asm volatile("cp.async.wait_group 0;" ::: "memory");
        __syncthreads();   // this pass's weights visible; prior reads complete

        const float x0 = ph ? p0 : q0;
        const float x1 = ph ? p1 : q1;

        float acc[2][NT][4];

        // ---- GEMM0: h1 = [x0,x1,tt,1] @ [W1|b1]^T  (mt: 0 -> t, 1 -> 0) ----
        {
            uint32_t bh[4][4];
#pragma unroll
            for (int g = 0; g < 4; ++g) ldsm4(bh[g], bW1h + g * 512);
#pragma unroll
            for (int mt = 0; mt < 2; ++mt)
#pragma unroll
                for (int nt = 0; nt < NT; ++nt)
#pragma unroll
                    for (int c = 0; c < 4; ++c) acc[mt][nt][c] = 0.f;

            const float xa0 = __shfl_sync(0xffffffffu, x0, r0);
            const float xa1 = __shfl_sync(0xffffffffu, x1, r0);
            const float xb0 = __shfl_sync(0xffffffffu, x0, r1);
            const float xb1 = __shfl_sync(0xffffffffu, x1, r1);
            const float ta  = __shfl_sync(0xffffffffu, tval, r0);
            const float tb  = __shfl_sync(0xffffffffu, tval, r1);
#pragma unroll
            for (int mt = 0; mt < 2; ++mt) {
                uint32_t a0 = 0u, a1 = 0u;
                if ((l & 3) == 0)      { a0 = pack_bf2(xa0, xa1); a1 = pack_bf2(xb0, xb1); }
                else if ((l & 3) == 1) { a0 = pack_bf2(mt ? 0.f : ta, 1.f);
                                         a1 = pack_bf2(mt ? 0.f : tb, 1.f); }
#pragma unroll
                for (int nt = 0; nt < NT; ++nt)
                    mma16808(acc[mt][nt], a0, a1, bh[nt >> 2][nt & 3]);
            }
        }

        // ---- sin -> GEMM1 A-fragments + fragment-order scratch (STS.64) ----
        uint32_t spk[2][NT][2];
#pragma unroll
        for (int mt = 0; mt < 2; ++mt)
#pragma unroll
            for (int nt = 0; nt < NT; ++nt) {
                spk[mt][nt][0] = pack_bf2(sinp(acc[mt][nt][0]), sinp(acc[mt][nt][1]));
                spk[mt][nt][1] = pack_bf2(sinp(acc[mt][nt][2]), sinp(acc[mt][nt][3]));
                asm volatile("st.shared.v2.u32 [%0], {%1,%2};"
                             :: "r"(sScr + (mt * NT + nt) * 256),
                                "r"(spk[mt][nt][0]), "r"(spk[mt][nt][1]));
            }

        // ---- GEMM1: H2 = S @ W2^T (+b2 via k=104 one-column) ----
#pragma unroll
        for (int mt = 0; mt < 2; ++mt)
#pragma unroll
            for (int nt = 0; nt < NT; ++nt)
#pragma unroll
                for (int c = 0; c < 4; ++c) acc[mt][nt][c] = 0.f;
#pragma unroll
        for (int kt = 0; kt < KT; ++kt) {
            uint32_t b[NTP][4];
#pragma unroll
            for (int np = 0; np < NTP; ++np)
                ldsm4(b[np], bW2 + 32 * kt + np * 16 * SPB);
#pragma unroll
            for (int mt = 0; mt < 2; ++mt) {
                uint32_t a[4];
                a[0] = spk[mt][2 * kt][0];
                a[1] = spk[mt][2 * kt][1];
                a[2] = (kt < 6) ? spk[mt][2 * kt + 1][0] : biasA;
                a[3] = (kt < 6) ? spk[mt][2 * kt + 1][1] : biasA;
#pragma unroll
                for (int np = 0; np < NTP; ++np) {
                    mma16816(acc[mt][2 * np], a, b[np][0], b[np][1]);
                    if (2 * np + 1 < NT)
                        mma16816(acc[mt][2 * np + 1], a, b[np][2], b[np][3]);
                }
            }
        }

        // ---- stage3 (packed bf16x2): g2 = (1 - h2^2/2) * w3 ----
        uint32_t af[2][KT][4];
#pragma unroll
        for (int nt = 0; nt < NT; ++nt) {
            const uint32_t wpk = w3pk[4 * nt + (l & 3)];
#pragma unroll
            for (int mt = 0; mt < 2; ++mt) {
                uint32_t h01 = pack_bf2(acc[mt][nt][0], acc[mt][nt][1]);
                uint32_t h23 = pack_bf2(acc[mt][nt][2], acc[mt][nt][3]);
                uint32_t g01 = hmul2u(hfma2u(hmul2u(h01, h01), NEGH2, ONE2), wpk);
                uint32_t g23 = hmul2u(hfma2u(hmul2u(h23, h23), NEGH2, ONE2), wpk);
                af[mt][nt >> 1][2 * (nt & 1) + 0] = g01;
                af[mt][nt >> 1][2 * (nt & 1) + 1] = g23;
            }
        }
#pragma unroll
        for (int mt = 0; mt < 2; ++mt) { af[mt][6][2] = 0u; af[mt][6][3] = 0u; }

        // ---- GEMM2: GC = G2 @ W2 (B = trans-ldsm of W2 tile) ----
#pragma unroll
        for (int mt = 0; mt < 2; ++mt)
#pragma unroll
            for (int nt = 0; nt < NT; ++nt)
#pragma unroll
                for (int c = 0; c < 4; ++c) acc[mt][nt][c] = 0.f;
#pragma unroll
        for (int kt = 0; kt < KT; ++kt) {
            uint32_t b[NTP][4];
#pragma unroll
            for (int np = 0; np < NTP; ++np)
                ldsm4t(b[np], bW2t + 16 * kt * SPB + 32 * np);
#pragma unroll
            for (int mt = 0; mt < 2; ++mt)
#pragma unroll
                for (int np = 0; np < NTP; ++np) {
                    mma16816(acc[mt][2 * np], af[mt][kt], b[np][0], b[np][1]);
                    if (2 * np + 1 < NT)
                        mma16816(acc[mt][2 * np + 1], af[mt][kt], b[np][2], b[np][3]);
                }
        }

        // ---- all warps done with W2/W1H/W3: prefetch next pass's weights ----
        __syncthreads();
        if (pass + 1 < NPASS) {
            const unsigned char* src = g_blob[pass + 1];
            for (int i = tid; i < REGA_BYTES / 16; i += TPB)
                cp16(sbase + SM_W2 + 16 * i, src + 16 * i);
            const uint32_t dstG = sbase + (((pass + 1) & 1) ? SM_W1G1 : SM_W1G0);
            for (int i = tid; i < 3840 / 16; i += TPB)
                cp16(dstG + 16 * i, src + OB_W1G + 16 * i);
            asm volatile("cp.async.commit_group;");
        }

        // ---- stage5 (packed): g1 = GC * (1 - s^2/2) from fragment scratch ----
        uint32_t af3[2][KT][4];
#pragma unroll
        for (int mt = 0; mt < 2; ++mt)
#pragma unroll
            for (int nt = 0; nt < NT; ++nt) {
                uint32_t u01, u23;
                asm("ld.shared.v2.u32 {%0,%1}, [%2];" : "=r"(u01), "=r"(u23)
                    : "r"(sScr + (mt * NT + nt) * 256));
                uint32_t c01 = hfma2u(hmul2u(u01, u01), NEGH2, ONE2);
                uint32_t c23 = hfma2u(hmul2u(u23, u23), NEGH2, ONE2);
                uint32_t a01 = pack_bf2(acc[mt][nt][0], acc[mt][nt][1]);
                uint32_t a23 = pack_bf2(acc[mt][nt][2], acc[mt][nt][3]);
                af3[mt][nt >> 1][2 * (nt & 1) + 0] = hmul2u(a01, c01);
                af3[mt][nt >> 1][2 * (nt & 1) + 1] = hmul2u(a23, c23);
            }
#pragma unroll
        for (int mt = 0; mt < 2; ++mt) { af3[mt][6][2] = 0u; af3[mt][6][3] = 0u; }

        // ---- GEMM3: grad = G1 @ W1[:, :2]  (current pass's W1G buffer) ----
        float acc3[2][4];
#pragma unroll
        for (int mt = 0; mt < 2; ++mt)
#pragma unroll
            for (int c = 0; c < 4; ++c) acc3[mt][c] = 0.f;
        {
            const uint32_t bW1g = sbase + ((pass & 1) ? SM_W1G1 : SM_W1G0) + bW1gL;
#pragma unroll
            for (int kt = 0; kt < KT; ++kt) {
                uint32_t bg[4];
                ldsm4(bg, bW1g + 32 * kt);
#pragma unroll
                for (int mt = 0; mt < 2; ++mt)
                    mma16816(acc3[mt], af3[mt][kt], bg[0], bg[1]);
            }
        }

        // ---- gg = grad(t) - grad(0): register diff + intra-warp shuffles ----
        float d0 = acc3[0][0] - acc3[1][0];
        float d1 = acc3[0][1] - acc3[1][1];
        float d2 = acc3[0][2] - acc3[1][2];
        float d3 = acc3[0][3] - acc3[1][3];
        const int h = 4 * (el & 7);
        float s0 = __shfl_sync(0xffffffffu, d0, h);
        float s1 = __shfl_sync(0xffffffffu, d1, h);
        float s2 = __shfl_sync(0xffffffffu, d2, h);
        float s3 = __shfl_sync(0xffffffffu, d3, h);
        const float g0 = (el < 8) ? s0 : s2;
        const float g1 = (el < 8) ? s1 : s3;
        if (ph == 0) { p0 -= g0; p1 -= g1; }
        else         { q0 += g0; q1 += g1; }
    }

    if (l < 16)
        reinterpret_cast<float4*>(out)[grow] = make_float4(q0, q1, p0, p1);
}

// ------------------------------------------------------------------
extern "C" void kernel_launch(void* const* d_in, const int* in_sizes, int n_in,
                              void* d_out, int out_size)
{
    const float* z   = (const float*)d_in[0];
    const float* t   = (const float*)d_in[1];
    const float* Wq1 = (const float*)d_in[2];
    const float* bq1 = (const float*)d_in[3];
    const float* Wq2 = (const float*)d_in[4];
    const float* bq2 = (const float*)d_in[5];
    const float* wq3 = (const float*)d_in[6];
    const float* Wp1 = (const float*)d_in[7];
    const float* bp1 = (const float*)d_in[8];
    const float* Wp2 = (const float*)d_in[9];
    const float* bp2 = (const float*)d_in[10];
    const float* wp3 = (const float*)d_in[11];
    float* out = (float*)d_out;

    cudaFuncSetAttribute(sympnet_mma_kernel,
                         cudaFuncAttributeMaxDynamicSharedMemorySize, SM_TOTAL);

    prep_kernel<<<NPASS, 256>>>(Wq1, bq1, Wq2, bq2, wq3, Wp1, bp1, Wp2, bp2, wp3);
    sympnet_mma_kernel<<<NBATCH / TILEB, TPB, SM_TOTAL>>>(z, t, out);
}

// round 11
// speedup vs baseline: 2.0052x; 1.0350x over previous
#include <cuda_runtime.h>
#include <cuda_bf16.h>
#include <cstdint>

#define NBATCH 131072
#define NH   100
#define SP   120           // W2 tile pitch (bf16) = 240B, ldmatrix conflict-free
#define SPB  (SP * 2)
#define TPB  128
#define TILEB 64
#define NPASS 6
#define KT   7             // k16 tiles
#define NT   13            // n8 tiles (104 >= 100)
#define NTP  7

// ---- SMEM layout ----
#define SM_SCR   0                      // 4 warps x 26 pairs x 32 lanes x 8B = 26624
#define SM_W2    26624                  // 112 x SP bf16 = 26880 (b2 folded in col 104)
#define SM_W1H   53504                  // 128 rows x 16B = 2048
#define SM_W3    55552                  // packed bf16x2 w3: 256
#define SM_W1G0  55808                  // 16 rows x 240B = 3840 (double buffered)
#define SM_W1G1  59648                  // 3840
#define SM_TOTAL 63488                  // -> 3 CTAs/SM

// ---- weight blob: [ W2 | W1H | W3pk ] (region A) + [ W1G ] (region B) ----
#define OB_W1H 26880
#define OB_W3  28928
#define REGA_BYTES 29184
#define OB_W1G 29184
#define BLOB_BYTES 33024

__device__ __align__(16) unsigned char g_blob[NPASS][BLOB_BYTES];

__device__ __forceinline__ uint32_t smem_u32(const void* p) {
    uint32_t a;
    asm("{ .reg .u64 t; cvta.to.shared.u64 t, %1; cvt.u32.u64 %0, t; }" : "=r"(a) : "l"(p));
    return a;
}
__device__ __forceinline__ void ldsm4(uint32_t* r, uint32_t addr) {
    asm volatile("ldmatrix.sync.aligned.m8n8.x4.shared.b16 {%0,%1,%2,%3}, [%4];"
                 : "=r"(r[0]), "=r"(r[1]), "=r"(r[2]), "=r"(r[3]) : "r"(addr));
}
__device__ __forceinline__ void ldsm4t(uint32_t* r, uint32_t addr) {
    asm volatile("ldmatrix.sync.aligned.m8n8.x4.trans.shared.b16 {%0,%1,%2,%3}, [%4];"
                 : "=r"(r[0]), "=r"(r[1]), "=r"(r[2]), "=r"(r[3]) : "r"(addr));
}
// accumulate: d += a@b
__device__ __forceinline__ void mma16816(float* d, const uint32_t* a, uint32_t b0, uint32_t b1) {
    asm volatile("mma.sync.aligned.m16n8k16.row.col.f32.bf16.bf16.f32 "
                 "{%0,%1,%2,%3}, {%4,%5,%6,%7}, {%8,%9}, {%0,%1,%2,%3};"
                 : "+f"(d[0]), "+f"(d[1]), "+f"(d[2]), "+f"(d[3])
                 : "r"(a[0]), "r"(a[1]), "r"(a[2]), "r"(a[3]), "r"(b0), "r"(b1));
}
// init: d = a@b + c  (c = shared zero quad; kills acc-zeroing MOVs)
__device__ __forceinline__ void mma16816i(float* d, const uint32_t* a, uint32_t b0, uint32_t b1,
                                          const float* c) {
    asm volatile("mma.sync.aligned.m16n8k16.row.col.f32.bf16.bf16.f32 "
                 "{%0,%1,%2,%3}, {%4,%5,%6,%7}, {%8,%9}, {%10,%11,%12,%13};"
                 : "=f"(d[0]), "=f"(d[1]), "=f"(d[2]), "=f"(d[3])
                 : "r"(a[0]), "r"(a[1]), "r"(a[2]), "r"(a[3]), "r"(b0), "r"(b1),
                   "f"(c[0]), "f"(c[1]), "f"(c[2]), "f"(c[3]));
}
__device__ __forceinline__ void mma16808i(float* d, uint32_t a0, uint32_t a1, uint32_t b0,
                                          const float* c) {
    asm volatile("mma.sync.aligned.m16n8k8.row.col.f32.bf16.bf16.f32 "
                 "{%0,%1,%2,%3}, {%4,%5}, {%6}, {%7,%8,%9,%10};"
                 : "=f"(d[0]), "=f"(d[1]), "=f"(d[2]), "=f"(d[3])
                 : "r"(a0), "r"(a1), "r"(b0),
                   "f"(c[0]), "f"(c[1]), "f"(c[2]), "f"(c[3]));
}
__device__ __forceinline__ void cp16(uint32_t smem_dst, const void* gsrc) {
    asm volatile("cp.async.cg.shared.global [%0], [%1], 16;"
                 :: "r"(smem_dst), "l"(gsrc));
}
__device__ __forceinline__ uint32_t pack_bf2(float a, float b) {
    __nv_bfloat162 t = __floats2bfloat162_rn(a, b);
    return *reinterpret_cast<uint32_t*>(&t);
}
__device__ __forceinline__ uint32_t hmul2u(uint32_t a, uint32_t b) {
    __nv_bfloat162 r = __hmul2(*reinterpret_cast<__nv_bfloat162*>(&a),
                               *reinterpret_cast<__nv_bfloat162*>(&b));
    return *reinterpret_cast<uint32_t*>(&r);
}
__device__ __forceinline__ uint32_t hfma2u(uint32_t a, uint32_t b, uint32_t c) {
    __nv_bfloat162 r = __hfma2(*reinterpret_cast<__nv_bfloat162*>(&a),
                               *reinterpret_cast<__nv_bfloat162*>(&b),
                               *reinterpret_cast<__nv_bfloat162*>(&c));
    return *reinterpret_cast<uint32_t*>(&r);
}
#define NEGH2 0xBF00BF00u   // bf16x2 {-0.5,-0.5}
#define ONE2  0x3F803F80u   // bf16x2 {1,1}
#define M6TH  0xBE2BBE2Bu   // bf16x2 {-1/6,-1/6}

// ------------------------------------------------------------------
__global__ void prep_kernel(
    const float* __restrict__ Wq1, const float* __restrict__ bq1,
    const float* __restrict__ Wq2, const float* __restrict__ bq2,
    const float* __restrict__ wq3,
    const float* __restrict__ Wp1, const float* __restrict__ bp1,
    const float* __restrict__ Wp2, const float* __restrict__ bp2,
    const float* __restrict__ wp3)
{
    const int net = blockIdx.x, layer = net >> 1, ph = net & 1;
    const float* W1 = (ph ? Wp1 : Wq1) + layer * NH * 3;
    const float* b1 = (ph ? bp1 : bq1) + layer * NH;
    const float* W2 = (ph ? Wp2 : Wq2) + layer * NH * NH;
    const float* b2 = (ph ? bp2 : bq2) + layer * NH;
    const float* w3 = (ph ? wp3 : wq3) + layer * NH;
    unsigned char* blob = g_blob[net];
    const int tid = threadIdx.x;

    for (int i = tid; i < BLOB_BYTES / 4; i += blockDim.x)
        reinterpret_cast<uint32_t*>(blob)[i] = 0u;
    __syncthreads();

    for (int idx = tid; idx < NH * NH; idx += blockDim.x) {
        int n = idx / NH, k = idx % NH;
        *reinterpret_cast<__nv_bfloat16*>(blob + n * SPB + 2 * k) = __float2bfloat16(W2[idx]);
    }
    for (int n = tid; n < NH; n += blockDim.x)
        *reinterpret_cast<__nv_bfloat16*>(blob + n * SPB + 208) = __float2bfloat16(b2[n]); // k=104
    for (int j = tid; j < NH; j += blockDim.x) {
        __nv_bfloat16* r = reinterpret_cast<__nv_bfloat16*>(blob + OB_W1H + 16 * j);
        r[0] = __float2bfloat16(W1[3 * j]);
        r[1] = __float2bfloat16(W1[3 * j + 1]);
        r[2] = __float2bfloat16(W1[3 * j + 2]);
        r[3] = __float2bfloat16(b1[j]);
        *reinterpret_cast<__nv_bfloat16*>(blob + OB_W1G + 2 * j)       = __float2bfloat16(W1[3 * j]);
        *reinterpret_cast<__nv_bfloat16*>(blob + OB_W1G + 240 + 2 * j) = __float2bfloat16(W1[3 * j + 1]);
    }
    // packed bf16x2 w3: idx 4nt+c -> (w3[8nt+2c], w3[8nt+2c+1])
    for (int i = tid; i < 52; i += blockDim.x) {
        int n = 8 * (i >> 2) + 2 * (i & 3);
        uint32_t v = 0u;
        if (n + 1 < NH) {
            __nv_bfloat162 t = __floats2bfloat162_rn(w3[n], w3[n + 1]);
            v = *reinterpret_cast<uint32_t*>(&t);
        }
        reinterpret_cast<uint32_t*>(blob + OB_W3)[i] = v;
    }
}

// ------------------------------------------------------------------
__global__ __launch_bounds__(TPB, 3)
void sympnet_mma_kernel(const float* __restrict__ z, const float* __restrict__ tcol,
                        float* __restrict__ out)
{
    extern __shared__ unsigned char smem[];
    const uint32_t sbase = smem_u32(smem);

    const int tid = threadIdx.x;
    const int w = tid >> 5, l = tid & 31;
    const int el = l & 15;               // batch element within warp (lanes 16-31 duplicate)
    const int grow = blockIdx.x * TILEB + 16 * w + el;

    // prologue: prefetch pass-0 weights
    {
        const unsigned char* src = g_blob[0];
        for (int i = tid; i < REGA_BYTES / 16; i += TPB)
            cp16(sbase + SM_W2 + 16 * i, src + 16 * i);
        for (int i = tid; i < 3840 / 16; i += TPB)
            cp16(sbase + SM_W1G0 + 16 * i, src + OB_W1G + 16 * i);
        asm volatile("cp.async.commit_group;");
    }

    const float4 z4 = reinterpret_cast<const float4*>(z)[grow];
    float q0 = z4.x, q1 = z4.y, p0 = z4.z, p1 = z4.w;
    const float tval = tcol[grow];

    // ldmatrix / scratch bases
    const uint32_t bW2  = sbase + SM_W2  + ((l & 7) + 8 * (l >> 4)) * SPB + 16 * ((l >> 3) & 1);
    const uint32_t bW2t = sbase + SM_W2  + ((l & 7) + 8 * ((l >> 3) & 1)) * SPB + 16 * (l >> 4);
    const uint32_t bW1h = sbase + SM_W1H + ((l & 7) + 8 * (l >> 3)) * 16;
    const uint32_t bW1gL = ((l & 7) + 8 * (l >> 4)) * 240 + 16 * ((l >> 3) & 1);
    const uint32_t sScr = sbase + SM_SCR + w * 6656 + l * 8;   // fragment-order S scratch

    const uint32_t* w3pk = reinterpret_cast<const uint32_t*>(smem + SM_W3);
    const uint32_t biasA = ((l & 3) == 0) ? 0x00003F80u : 0u;   // bf16 1.0 at k=104
    const int r0 = l >> 2, r1 = r0 + 8;
    const float zc[4] = {0.f, 0.f, 0.f, 0.f};

#pragma unroll 1
    for (int pass = 0; pass < NPASS; ++pass) {
        const int ph = pass & 1;

        asm volatile("cp.async.wait_group 0;" ::: "memory");
        __syncthreads();   // this pass's weights visible; prior reads complete

        const float x0 = ph ? p0 : q0;
        const float x1 = ph ? p1 : q1;

        float acc[2][NT][4];

        // ---- GEMM0: h1 = [x0,x1,tt,1] @ [W1|b1]^T  (mt: 0 -> t, 1 -> 0) ----
        {
            uint32_t bh[4][4];
#pragma unroll
            for (int g = 0; g < 4; ++g) ldsm4(bh[g], bW1h + g * 512);

            const float xa0 = __shfl_sync(0xffffffffu, x0, r0);
            const float xa1 = __shfl_sync(0xffffffffu, x1, r0);
            const float xb0 = __shfl_sync(0xffffffffu, x0, r1);
            const float xb1 = __shfl_sync(0xffffffffu, x1, r1);
            const float ta  = __shfl_sync(0xffffffffu, tval, r0);
            const float tb  = __shfl_sync(0xffffffffu, tval, r1);
#pragma unroll
            for (int mt = 0; mt < 2; ++mt) {
                uint32_t a0 = 0u, a1 = 0u;
                if ((l & 3) == 0)      { a0 = pack_bf2(xa0, xa1); a1 = pack_bf2(xb0, xb1); }
                else if ((l & 3) == 1) { a0 = pack_bf2(mt ? 0.f : ta, 1.f);
                                         a1 = pack_bf2(mt ? 0.f : tb, 1.f); }
#pragma unroll
                for (int nt = 0; nt < NT; ++nt)
                    mma16808i(acc[mt][nt], a0, a1, bh[nt >> 2][nt & 3], zc);
            }
        }

        // ---- sin (packed bf16x2) -> GEMM1 A-fragments + fragment scratch ----
        uint32_t spk[2][NT][2];
#pragma unroll
        for (int mt = 0; mt < 2; ++mt)
#pragma unroll
            for (int nt = 0; nt < NT; ++nt) {
                uint32_t h01 = pack_bf2(acc[mt][nt][0], acc[mt][nt][1]);
                uint32_t h23 = pack_bf2(acc[mt][nt][2], acc[mt][nt][3]);
                spk[mt][nt][0] = hmul2u(h01, hfma2u(hmul2u(h01, h01), M6TH, ONE2));
                spk[mt][nt][1] = hmul2u(h23, hfma2u(hmul2u(h23, h23), M6TH, ONE2));
                asm volatile("st.shared.v2.u32 [%0], {%1,%2};"
                             :: "r"(sScr + (mt * NT + nt) * 256),
                                "r"(spk[mt][nt][0]), "r"(spk[mt][nt][1]));
            }

        // ---- GEMM1: H2 = S @ W2^T (+b2 via k=104 one-column) ----
#pragma unroll
        for (int kt = 0; kt < KT; ++kt) {
            uint32_t b[NTP][4];
#pragma unroll
            for (int np = 0; np < NTP; ++np)
                ldsm4(b[np], bW2 + 32 * kt + np * 16 * SPB);
#pragma unroll
            for (int mt = 0; mt < 2; ++mt) {
                uint32_t a[4];
                a[0] = spk[mt][2 * kt][0];
                a[1] = spk[mt][2 * kt][1];
                a[2] = (kt < 6) ? spk[mt][2 * kt + 1][0] : biasA;
                a[3] = (kt < 6) ? spk[mt][2 * kt + 1][1] : biasA;
#pragma unroll
                for (int np = 0; np < NTP; ++np) {
                    if (kt == 0) {
                        mma16816i(acc[mt][2 * np], a, b[np][0], b[np][1], zc);
                        if (2 * np + 1 < NT)
                            mma16816i(acc[mt][2 * np + 1], a, b[np][2], b[np][3], zc);
                    } else {
                        mma16816(acc[mt][2 * np], a, b[np][0], b[np][1]);
                        if (2 * np + 1 < NT)
                            mma16816(acc[mt][2 * np + 1], a, b[np][2], b[np][3]);
                    }
                }
            }
        }

        // ---- stage3 (packed bf16x2): g2 = (1 - h2^2/2) * w3 ----
        uint32_t af[2][KT][4];
#pragma unroll
        for (int nt = 0; nt < NT; ++nt) {
            const uint32_t wpk = w3pk[4 * nt + (l & 3)];
#pragma unroll
            for (int mt = 0; mt < 2; ++mt) {
                uint32_t h01 = pack_bf2(acc[mt][nt][0], acc[mt][nt][1]);
                uint32_t h23 = pack_bf2(acc[mt][nt][2], acc[mt][nt][3]);
                uint32_t g01 = hmul2u(hfma2u(hmul2u(h01, h01), NEGH2, ONE2), wpk);
                uint32_t g23 = hmul2u(hfma2u(hmul2u(h23, h23), NEGH2, ONE2), wpk);
                af[mt][nt >> 1][2 * (nt & 1) + 0] = g01;
                af[mt][nt >> 1][2 * (nt & 1) + 1] = g23;
            }
        }
#pragma unroll
        for (int mt = 0; mt < 2; ++mt) { af[mt][6][2] = 0u; af[mt][6][3] = 0u; }

        // ---- GEMM2: GC = G2 @ W2 (B = trans-ldsm of W2 tile) ----
#pragma unroll
        for (int kt = 0; kt < KT; ++kt) {
            uint32_t b[NTP][4];
#pragma unroll
            for (int np = 0; np < NTP; ++np)
                ldsm4t(b[np], bW2t + 16 * kt * SPB + 32 * np);
#pragma unroll
            for (int mt = 0; mt < 2; ++mt)
#pragma unroll
                for (int np = 0; np < NTP; ++np) {
                    if (kt == 0) {
                        mma16816i(acc[mt][2 * np], af[mt][0], b[np][0], b[np][1], zc);
                        if (2 * np + 1 < NT)
                            mma16816i(acc[mt][2 * np + 1], af[mt][0], b[np][2], b[np][3], zc);
                    } else {
                        mma16816(acc[mt][2 * np], af[mt][kt], b[np][0], b[np][1]);
                        if (2 * np + 1 < NT)
                            mma16816(acc[mt][2 * np + 1], af[mt][kt], b[np][2], b[np][3]);
                    }
                }
        }

        // ---- all warps done with W2/W1H/W3: prefetch next pass's weights ----
        __syncthreads();
        if (pass + 1 < NPASS) {
            const unsigned char* src = g_blob[pass + 1];
            for (int i = tid; i < REGA_BYTES / 16; i += TPB)
                cp16(sbase + SM_W2 + 16 * i, src + 16 * i);
            const uint32_t dstG = sbase + (((pass + 1) & 1) ? SM_W1G1 : SM_W1G0);
            for (int i = tid; i < 3840 / 16; i += TPB)
                cp16(dstG + 16 * i, src + OB_W1G + 16 * i);
            asm volatile("cp.async.commit_group;");
        }

        // ---- stage5 (packed): g1 = GC * (1 - s^2/2) from fragment scratch ----
        uint32_t af3[2][KT][4];
#pragma unroll
        for (int mt = 0; mt < 2; ++mt)
#pragma unroll
            for (int nt = 0; nt < NT; ++nt) {
                uint32_t u01, u23;
                asm("ld.shared.v2.u32 {%0,%1}, [%2];" : "=r"(u01), "=r"(u23)
                    : "r"(sScr + (mt * NT + nt) * 256));
                uint32_t c01 = hfma2u(hmul2u(u01, u01), NEGH2, ONE2);
                uint32_t c23 = hfma2u(hmul2u(u23, u23), NEGH2, ONE2);
                uint32_t a01 = pack_bf2(acc[mt][nt][0], acc[mt][nt][1]);
                uint32_t a23 = pack_bf2(acc[mt][nt][2], acc[mt][nt][3]);
                af3[mt][nt >> 1][2 * (nt & 1) + 0] = hmul2u(a01, c01);
                af3[mt][nt >> 1][2 * (nt & 1) + 1] = hmul2u(a23, c23);
            }
#pragma unroll
        for (int mt = 0; mt < 2; ++mt) { af3[mt][6][2] = 0u; af3[mt][6][3] = 0u; }

        // ---- GEMM3: grad = G1 @ W1[:, :2]  (current pass's W1G buffer) ----
        float acc3[2][4];
        {
            const uint32_t bW1g = sbase + ((pass & 1) ? SM_W1G1 : SM_W1G0) + bW1gL;
#pragma unroll
            for (int kt = 0; kt < KT; ++kt) {
                uint32_t bg[4];
                ldsm4(bg, bW1g + 32 * kt);
#pragma unroll
                for (int mt = 0; mt < 2; ++mt) {
                    if (kt == 0) mma16816i(acc3[mt], af3[mt][0], bg[0], bg[1], zc);
                    else         mma16816 (acc3[mt], af3[mt][kt], bg[0], bg[1]);
                }
            }
        }

        // ---- gg = grad(t) - grad(0): register diff + intra-warp shuffles ----
        float d0 = acc3[0][0] - acc3[1][0];
        float d1 = acc3[0][1] - acc3[1][1];
        float d2 = acc3[0][2] - acc3[1][2];
        float d3 = acc3[0][3] - acc3[1][3];
        const int h = 4 * (el & 7);
        float s0 = __shfl_sync(0xffffffffu, d0, h);
        float s1 = __shfl_sync(0xffffffffu, d1, h);
        float s2 = __shfl_sync(0xffffffffu, d2, h);
        float s3 = __shfl_sync(0xffffffffu, d3, h);
        const float g0 = (el < 8) ? s0 : s2;
        const float g1 = (el < 8) ? s1 : s3;
        if (ph == 0) { p0 -= g0; p1 -= g1; }
        else         { q0 += g0; q1 += g1; }
    }

    if (l < 16)
        reinterpret_cast<float4*>(out)[grow] = make_float4(q0, q1, p0, p1);
}

// ------------------------------------------------------------------
extern "C" void kernel_launch(void* const* d_in, const int* in_sizes, int n_in,
                              void* d_out, int out_size)
{
    const float* z   = (const float*)d_in[0];
    const float* t   = (const float*)d_in[1];
    const float* Wq1 = (const float*)d_in[2];
    const float* bq1 = (const float*)d_in[3];
    const float* Wq2 = (const float*)d_in[4];
    const float* bq2 = (const float*)d_in[5];
    const float* wq3 = (const float*)d_in[6];
    const float* Wp1 = (const float*)d_in[7];
    const float* bp1 = (const float*)d_in[8];
    const float* Wp2 = (const float*)d_in[9];
    const float* bp2 = (const float*)d_in[10];
    const float* wp3 = (const float*)d_in[11];
    float* out = (float*)d_out;

    cudaFuncSetAttribute(sympnet_mma_kernel,
                         cudaFuncAttributeMaxDynamicSharedMemorySize, SM_TOTAL);

    prep_kernel<<<NPASS, 256>>>(Wq1, bq1, Wq2, bq2, wq3, Wp1, bp1, Wp2, bp2, wp3);
    sympnet_mma_kernel<<<NBATCH / TILEB, TPB, SM_TOTAL>>>(z, t, out);
}